// round 2
// baseline (speedup 1.0000x reference)
#include <cuda_runtime.h>
#include <cstdint>

// Problem constants (B=1, H=8, S=1024, D=64, KG=10)
#define SS   1024
#define DH   64
#define NH   8
#define NKG  10
#define LUTN 4096
#define BM   64
#define BN   64

// ---------------------------------------------------------------------------
// Scratch: LUTs for the two scalar bias functions f_D(x), f_E(x)
// ---------------------------------------------------------------------------
__device__ float g_lutD[LUTN];
__device__ float g_lutE[LUTN];
__device__ float g_rng[4];  // loD, invhD, loE, invhE

// ---------------------------------------------------------------------------
// Kernel 1: build the two bias LUTs. bias(x) = W2 @ gelu(W1 @ psi(x) + b1) + b2
// where psi_k(x) = N(x + b_k ; mu_k, sigma_k). Pure scalar function of x.
// Range covers +-12 sigma of every kernel center; outside, psi underflows to 0
// so clamping to the LUT edge is exact.
// ---------------------------------------------------------------------------
__global__ void build_lut_kernel(
    const float* __restrict__ muD, const float* __restrict__ sgD, const float* __restrict__ bD,
    const float* __restrict__ muE, const float* __restrict__ sgE, const float* __restrict__ bE,
    const float* __restrict__ W1, const float* __restrict__ b1,
    const float* __restrict__ W2, const float* __restrict__ b2)
{
    const int which = blockIdx.x;            // 0 => D, 1 => E
    const float* mu = which ? muE : muD;
    const float* sg = which ? sgE : sgD;
    const float* bb = which ? bE  : bD;
    float* lut      = which ? g_lutE : g_lutD;

    __shared__ float sW1[NKG * NKG], sb1[NKG], sW2[NKG], sb2;
    if (threadIdx.x < NKG * NKG) sW1[threadIdx.x] = W1[threadIdx.x];
    if (threadIdx.x < NKG) { sb1[threadIdx.x] = b1[threadIdx.x]; sW2[threadIdx.x] = W2[threadIdx.x]; }
    if (threadIdx.x == 0) sb2 = b2[0];

    float mus[NKG], sgs[NKG], bbs[NKG], inorm[NKG];
    float lo = 1e30f, hi = -1e30f;
    #pragma unroll
    for (int k = 0; k < NKG; ++k) {
        mus[k] = mu[k]; sgs[k] = sg[k]; bbs[k] = bb[k];
        inorm[k] = 0.3989422804014327f / sgs[k];
        float c = mus[k] - bbs[k];
        lo = fminf(lo, c - 12.f * sgs[k]);
        hi = fmaxf(hi, c + 12.f * sgs[k]);
    }
    __syncthreads();

    const float step = (hi - lo) / (float)(LUTN - 1);
    for (int i = threadIdx.x; i < LUTN; i += blockDim.x) {
        float x = lo + step * (float)i;
        float psi[NKG];
        #pragma unroll
        for (int k = 0; k < NKG; ++k) {
            float z = (x + bbs[k] - mus[k]) / sgs[k];
            psi[k] = expf(-0.5f * z * z) * inorm[k];
        }
        float f = sb2;
        #pragma unroll
        for (int l = 0; l < NKG; ++l) {
            float u = sb1[l];
            #pragma unroll
            for (int k = 0; k < NKG; ++k)
                u = fmaf(sW1[l * NKG + k], psi[k], u);
            // exact gelu: 0.5*u*(1+erf(u/sqrt(2)))
            float g = 0.5f * u * (1.0f + erff(u * 0.70710678118654752f));
            f = fmaf(sW2[l], g, f);
        }
        lut[i] = f;
    }
    if (threadIdx.x == 0) {
        float invh = (float)(LUTN - 1) / (hi - lo);
        if (which) { g_rng[2] = lo; g_rng[3] = invh; }
        else       { g_rng[0] = lo; g_rng[1] = invh; }
    }
}

// ---------------------------------------------------------------------------
// Kernel 2: fused flash attention with LUT bias.
// Grid (S/BM, H) = (16, 8). 256 threads, thread (ty,tx) in 16x16 grid owns a
// 4x4 micro-tile: rows r0=4*ty of the Q row-tile, cols c0=4*tx of the current
// key tile (and of the D output). Smem tiles are XOR-chunk-swizzled so every
// GEMM-side shared load is conflict-free.
// ---------------------------------------------------------------------------
__global__ void __launch_bounds__(256, 2) attn_kernel(
    const float* __restrict__ Q, const float* __restrict__ K, const float* __restrict__ V,
    const float* __restrict__ dist, const float* __restrict__ ener,
    const int* __restrict__ mask, float* __restrict__ out)
{
    extern __shared__ float smem[];
    float* sq   = smem;            // [64][64]  Q tile (pre-scaled), natural layout
    float* skt  = smem + 4096;     // [64][64]  K^T tile: row k holds K[:,k], chunk-swizzled by k
    float* sv   = smem + 8192;     // [64][64]  V tile, natural rows, chunk-swizzled by row
    float* sp   = smem + 12288;    // [64][64]  P tile, natural rows, chunk-swizzled by row
    float* lutD = smem + 16384;    // [4096]
    float* lutE = smem + 20480;    // [4096]

    const int t    = threadIdx.x;
    const int head = blockIdx.y;
    const int i0   = blockIdx.x * BM;
    const int tx   = t & 15;
    const int ty   = t >> 4;
    const int r0   = ty << 2;
    const int c0   = tx << 2;

    // stage LUTs into shared
    for (int i = t; i < LUTN; i += 256) { lutD[i] = g_lutD[i]; lutE[i] = g_lutE[i]; }

    // stage Q tile (scaled by 1/sqrt(2*D))
    {
        const float qscale = 0.08838834764831845f;   // 1/sqrt(128)
        const float4* qg = (const float4*)(Q + (size_t)(head * SS + i0) * DH);
        float4* qs = (float4*)sq;
        for (int i = t; i < BM * DH / 4; i += 256) {
            float4 v = qg[i];
            v.x *= qscale; v.y *= qscale; v.z *= qscale; v.w *= qscale;
            qs[i] = v;
        }
    }
    const float loD = g_rng[0], ihD = g_rng[1], loE = g_rng[2], ihE = g_rng[3];

    float acc[4][4];
    #pragma unroll
    for (int i = 0; i < 4; ++i)
        #pragma unroll
        for (int d = 0; d < 4; ++d) acc[i][d] = 0.f;
    float mrow[4] = {-1e30f, -1e30f, -1e30f, -1e30f};
    float lrow[4] = {0.f, 0.f, 0.f, 0.f};

    for (int jt = 0; jt < SS / BN; ++jt) {
        const int j0 = jt * BN;
        __syncthreads();   // previous iteration's PV reads done before overwriting K/V

        // ---- load K tile (transposed, swizzled) + V tile (swizzled) ----
        {
            const int c  = t >> 2;       // 0..63 : source row index
            const int q4 = t & 3;
            const float4* krow = (const float4*)(K + (size_t)(head * SS + j0 + c) * DH);
            const float4* vrow = (const float4*)(V + (size_t)(head * SS + j0 + c) * DH);
            const int cs = c >> 2, ce = c & 3;
            #pragma unroll
            for (int m = q4; m < 16; m += 4) {
                float4 kv = krow[m];
                int k0 = m << 2;
                skt[(k0 + 0) * 64 + (((cs ^ ((k0 + 0) & 7)) << 2) | ce)] = kv.x;
                skt[(k0 + 1) * 64 + (((cs ^ ((k0 + 1) & 7)) << 2) | ce)] = kv.y;
                skt[(k0 + 2) * 64 + (((cs ^ ((k0 + 2) & 7)) << 2) | ce)] = kv.z;
                skt[(k0 + 3) * 64 + (((cs ^ ((k0 + 3) & 7)) << 2) | ce)] = kv.w;
                float4 vv = vrow[m];
                ((float4*)sv)[c * 16 + (m ^ (c & 7))] = vv;
            }
        }
        __syncthreads();

        // ---- S = (Q * scale) @ K^T ----
        float s[4][4];
        #pragma unroll
        for (int i = 0; i < 4; ++i)
            #pragma unroll
            for (int c = 0; c < 4; ++c) s[i][c] = 0.f;

        #pragma unroll 4
        for (int k = 0; k < DH; k += 4) {
            float a[4][4], b[4][4];
            #pragma unroll
            for (int i = 0; i < 4; ++i)
                *(float4*)a[i] = *(const float4*)&sq[(r0 + i) * 64 + k];
            #pragma unroll
            for (int kk = 0; kk < 4; ++kk)
                *(float4*)b[kk] = *(const float4*)&skt[(k + kk) * 64 + ((tx ^ ((k + kk) & 7)) << 2)];
            #pragma unroll
            for (int kk = 0; kk < 4; ++kk)
                #pragma unroll
                for (int i = 0; i < 4; ++i)
                    #pragma unroll
                    for (int c = 0; c < 4; ++c)
                        s[i][c] = fmaf(a[i][kk], b[kk][c], s[i][c]);
        }

        // ---- bias (LUT) + mask ----
        #pragma unroll
        for (int i = 0; i < 4; ++i) {
            size_t rowoff = ((size_t)head * SS + (size_t)(i0 + r0 + i)) * SS + (size_t)(j0 + c0);
            float4 d4 = *(const float4*)(dist + rowoff);
            float4 e4 = *(const float4*)(ener + rowoff);
            int4  mk4 = *(const int4*)(mask + rowoff);
            float dx[4] = {d4.x, d4.y, d4.z, d4.w};
            float ex[4] = {e4.x, e4.y, e4.z, e4.w};
            int   mm[4] = {mk4.x, mk4.y, mk4.z, mk4.w};
            #pragma unroll
            for (int c = 0; c < 4; ++c) {
                float v = s[i][c];
                float u = (dx[c] - loD) * ihD;
                u = fminf(fmaxf(u, 0.f), (float)(LUTN - 1));
                int ii = min((int)u, LUTN - 2);
                float fr = u - (float)ii;
                float va = lutD[ii];
                v += fmaf(lutD[ii + 1] - va, fr, va);

                u = (ex[c] - loE) * ihE;
                u = fminf(fmaxf(u, 0.f), (float)(LUTN - 1));
                ii = min((int)u, LUTN - 2);
                fr = u - (float)ii;
                va = lutE[ii];
                v += fmaf(lutE[ii + 1] - va, fr, va);

                s[i][c] = (mm[c] == 0) ? -1e9f : v;
            }
        }

        // ---- online softmax (row stats reduced across the 16 tx lanes) ----
        #pragma unroll
        for (int i = 0; i < 4; ++i) {
            float rmax = fmaxf(fmaxf(s[i][0], s[i][1]), fmaxf(s[i][2], s[i][3]));
            #pragma unroll
            for (int ofs = 8; ofs >= 1; ofs >>= 1)
                rmax = fmaxf(rmax, __shfl_xor_sync(0xffffffffu, rmax, ofs));
            float mnew = fmaxf(mrow[i], rmax);
            float corr = __expf(mrow[i] - mnew);
            mrow[i] = mnew;
            float p0 = __expf(s[i][0] - mnew);
            float p1 = __expf(s[i][1] - mnew);
            float p2 = __expf(s[i][2] - mnew);
            float p3 = __expf(s[i][3] - mnew);
            float rs = (p0 + p1) + (p2 + p3);
            #pragma unroll
            for (int ofs = 8; ofs >= 1; ofs >>= 1)
                rs += __shfl_xor_sync(0xffffffffu, rs, ofs);
            lrow[i] = lrow[i] * corr + rs;
            #pragma unroll
            for (int d = 0; d < 4; ++d) acc[i][d] *= corr;
            int r = r0 + i;
            ((float4*)sp)[r * 16 + (tx ^ (r & 7))] = make_float4(p0, p1, p2, p3);
        }
        __syncthreads();

        // ---- acc += P @ V ----
        #pragma unroll 4
        for (int j = 0; j < BN; j += 4) {
            float p[4][4], vv[4][4];
            #pragma unroll
            for (int i = 0; i < 4; ++i) {
                int r = r0 + i;
                *(float4*)p[i] = ((const float4*)sp)[r * 16 + ((j >> 2) ^ (r & 7))];
            }
            #pragma unroll
            for (int jj = 0; jj < 4; ++jj) {
                int vr = j + jj;
                *(float4*)vv[jj] = ((const float4*)sv)[vr * 16 + (tx ^ (vr & 7))];
            }
            #pragma unroll
            for (int jj = 0; jj < 4; ++jj)
                #pragma unroll
                for (int i = 0; i < 4; ++i)
                    #pragma unroll
                    for (int d = 0; d < 4; ++d)
                        acc[i][d] = fmaf(p[i][jj], vv[jj][d], acc[i][d]);
        }
    }

    // ---- normalize + store ----
    #pragma unroll
    for (int i = 0; i < 4; ++i) {
        float inv = 1.0f / lrow[i];
        float4 o = make_float4(acc[i][0] * inv, acc[i][1] * inv, acc[i][2] * inv, acc[i][3] * inv);
        *(float4*)(out + (size_t)(head * SS + i0 + r0 + i) * DH + c0) = o;
    }
}

// ---------------------------------------------------------------------------
// Launch
// ---------------------------------------------------------------------------
extern "C" void kernel_launch(void* const* d_in, const int* in_sizes, int n_in,
                              void* d_out, int out_size) {
    const float* Q    = (const float*)d_in[0];
    const float* K    = (const float*)d_in[1];
    const float* V    = (const float*)d_in[2];
    const float* dist = (const float*)d_in[3];
    const float* ener = (const float*)d_in[4];
    const int*   mask = (const int*)d_in[5];
    const float* muD  = (const float*)d_in[6];
    const float* sgD  = (const float*)d_in[7];
    const float* bD   = (const float*)d_in[8];
    const float* muE  = (const float*)d_in[9];
    const float* sgE  = (const float*)d_in[10];
    const float* bE   = (const float*)d_in[11];
    const float* W1   = (const float*)d_in[12];
    const float* b1   = (const float*)d_in[13];
    const float* W2   = (const float*)d_in[14];
    const float* b2   = (const float*)d_in[15];
    float* out = (float*)d_out;

    build_lut_kernel<<<2, 256>>>(muD, sgD, bD, muE, sgE, bE, W1, b1, W2, b2);

    const int smem_bytes = 24576 * sizeof(float);   // 96 KB
    cudaFuncSetAttribute(attn_kernel, cudaFuncAttributeMaxDynamicSharedMemorySize, smem_bytes);
    dim3 grid(SS / BM, NH);
    attn_kernel<<<grid, 256, smem_bytes>>>(Q, K, V, dist, ener, mask, out);
}

// round 3
// speedup vs baseline: 1.1669x; 1.1669x over previous
#include <cuda_runtime.h>
#include <cstdint>

// Problem constants (B=1, H=8, S=1024, D=64, KG=10)
#define SS    1024
#define DH    64
#define NH    8
#define NKG   10
#define LUTN  4096
#define BM    64
#define BN    64
#define SPLIT 2
#define SKEY  (SS / SPLIT)

// ---------------------------------------------------------------------------
// Device scratch (static allocations only — no cudaMalloc allowed)
// ---------------------------------------------------------------------------
__device__ float2 g_lut2D[LUTN];            // packed {f[i], f[i+1]}
__device__ float2 g_lut2E[LUTN];
__device__ float  g_rng[4];                 // loD, invhD, loE, invhE
__device__ float  g_pacc[SPLIT][NH][SS][DH];   // 4 MB partial accumulators
__device__ float  g_pm[SPLIT][NH][SS];
__device__ float  g_pl[SPLIT][NH][SS];

// ---------------------------------------------------------------------------
// Kernel 1: build packed bias LUTs. bias(x) = W2 @ gelu(W1 @ psi(x) + b1) + b2
// Range covers +-12 sigma of every kernel center; outside, psi underflows to 0
// so clamping to the LUT edge is exact.
// ---------------------------------------------------------------------------
__global__ void build_lut_kernel(
    const float* __restrict__ muD, const float* __restrict__ sgD, const float* __restrict__ bD,
    const float* __restrict__ muE, const float* __restrict__ sgE, const float* __restrict__ bE,
    const float* __restrict__ W1, const float* __restrict__ b1,
    const float* __restrict__ W2, const float* __restrict__ b2)
{
    const int which = blockIdx.x;            // 0 => D, 1 => E
    const float* mu = which ? muE : muD;
    const float* sg = which ? sgE : sgD;
    const float* bb = which ? bE  : bD;
    float2* lut2    = which ? g_lut2E : g_lut2D;

    __shared__ float sW1[NKG * NKG], sb1[NKG], sW2[NKG], sb2;
    __shared__ float slut[LUTN];
    if (threadIdx.x < NKG * NKG) sW1[threadIdx.x] = W1[threadIdx.x];
    if (threadIdx.x < NKG) { sb1[threadIdx.x] = b1[threadIdx.x]; sW2[threadIdx.x] = W2[threadIdx.x]; }
    if (threadIdx.x == 0) sb2 = b2[0];

    float mus[NKG], sgs[NKG], bbs[NKG], inorm[NKG];
    float lo = 1e30f, hi = -1e30f;
    #pragma unroll
    for (int k = 0; k < NKG; ++k) {
        mus[k] = mu[k]; sgs[k] = sg[k]; bbs[k] = bb[k];
        inorm[k] = 0.3989422804014327f / sgs[k];
        float c = mus[k] - bbs[k];
        lo = fminf(lo, c - 12.f * sgs[k]);
        hi = fmaxf(hi, c + 12.f * sgs[k]);
    }
    __syncthreads();

    const float step = (hi - lo) / (float)(LUTN - 1);
    for (int i = threadIdx.x; i < LUTN; i += blockDim.x) {
        float x = lo + step * (float)i;
        float psi[NKG];
        #pragma unroll
        for (int k = 0; k < NKG; ++k) {
            float z = (x + bbs[k] - mus[k]) / sgs[k];
            psi[k] = expf(-0.5f * z * z) * inorm[k];
        }
        float f = sb2;
        #pragma unroll
        for (int l = 0; l < NKG; ++l) {
            float u = sb1[l];
            #pragma unroll
            for (int k = 0; k < NKG; ++k)
                u = fmaf(sW1[l * NKG + k], psi[k], u);
            float g = 0.5f * u * (1.0f + erff(u * 0.70710678118654752f));
            f = fmaf(sW2[l], g, f);
        }
        slut[i] = f;
    }
    __syncthreads();
    for (int i = threadIdx.x; i < LUTN; i += blockDim.x) {
        float a = slut[i];
        float b = (i + 1 < LUTN) ? slut[i + 1] : a;
        lut2[i] = make_float2(a, b);
    }
    if (threadIdx.x == 0) {
        float invh = (float)(LUTN - 1) / (hi - lo);
        if (which) { g_rng[2] = lo; g_rng[3] = invh; }
        else       { g_rng[0] = lo; g_rng[1] = invh; }
    }
}

// ---------------------------------------------------------------------------
// Kernel 2: fused flash attention (split-KV partial) with LUT bias.
// Grid (S/BM, H, SPLIT) = (16, 8, 2). 256 threads, 4x4 micro-tiles.
// Writes unnormalized partial acc + per-row (m, l) for the merge kernel.
// ---------------------------------------------------------------------------
__global__ void __launch_bounds__(256, 2) attn_kernel(
    const float* __restrict__ Q, const float* __restrict__ K, const float* __restrict__ V,
    const float* __restrict__ dist, const float* __restrict__ ener,
    const int* __restrict__ mask)
{
    extern __shared__ float smem[];
    float* sq   = smem;            // [64][64]  Q tile (pre-scaled)
    float* skt  = smem + 4096;     // [64][64]  K^T tile, chunk-swizzled
    float* sv   = smem + 8192;     // [64][64]  V tile, chunk-swizzled
    float* sp   = smem + 12288;    // [64][64]  P tile, chunk-swizzled

    const int t    = threadIdx.x;
    const int head = blockIdx.y;
    const int i0   = blockIdx.x * BM;
    const int z    = blockIdx.z;
    const int tx   = t & 15;
    const int ty   = t >> 4;
    const int r0   = ty << 2;
    const int c0   = tx << 2;

    // stage Q tile (scaled by 1/sqrt(2*D))
    {
        const float qscale = 0.08838834764831845f;   // 1/sqrt(128)
        const float4* qg = (const float4*)(Q + (size_t)(head * SS + i0) * DH);
        float4* qs = (float4*)sq;
        for (int i = t; i < BM * DH / 4; i += 256) {
            float4 v = qg[i];
            v.x *= qscale; v.y *= qscale; v.z *= qscale; v.w *= qscale;
            qs[i] = v;
        }
    }
    const float loD = g_rng[0], ihD = g_rng[1], loE = g_rng[2], ihE = g_rng[3];

    float acc[4][4];
    #pragma unroll
    for (int i = 0; i < 4; ++i)
        #pragma unroll
        for (int d = 0; d < 4; ++d) acc[i][d] = 0.f;
    float mrow[4] = {-1e30f, -1e30f, -1e30f, -1e30f};
    float lrow[4] = {0.f, 0.f, 0.f, 0.f};

    for (int jt = 0; jt < SKEY / BN; ++jt) {
        const int j0 = z * SKEY + jt * BN;
        __syncthreads();   // previous iteration's PV reads done before overwriting K/V

        // ---- load K tile (transposed, swizzled) + V tile (swizzled) ----
        {
            const int c  = t >> 2;       // 0..63 : source row index
            const int q4 = t & 3;
            const float4* krow = (const float4*)(K + (size_t)(head * SS + j0 + c) * DH);
            const float4* vrow = (const float4*)(V + (size_t)(head * SS + j0 + c) * DH);
            const int cs = c >> 2, ce = c & 3;
            #pragma unroll
            for (int m = q4; m < 16; m += 4) {
                float4 kv = krow[m];
                int k0 = m << 2;
                skt[(k0 + 0) * 64 + (((cs ^ ((k0 + 0) & 7)) << 2) | ce)] = kv.x;
                skt[(k0 + 1) * 64 + (((cs ^ ((k0 + 1) & 7)) << 2) | ce)] = kv.y;
                skt[(k0 + 2) * 64 + (((cs ^ ((k0 + 2) & 7)) << 2) | ce)] = kv.z;
                skt[(k0 + 3) * 64 + (((cs ^ ((k0 + 3) & 7)) << 2) | ce)] = kv.w;
                float4 vv = vrow[m];
                ((float4*)sv)[c * 16 + (m ^ (c & 7))] = vv;
            }
        }
        __syncthreads();

        // ---- S = (Q * scale) @ K^T ----
        float s[4][4];
        #pragma unroll
        for (int i = 0; i < 4; ++i)
            #pragma unroll
            for (int c = 0; c < 4; ++c) s[i][c] = 0.f;

        #pragma unroll 4
        for (int k = 0; k < DH; k += 4) {
            float a[4][4], b[4][4];
            #pragma unroll
            for (int i = 0; i < 4; ++i)
                *(float4*)a[i] = *(const float4*)&sq[(r0 + i) * 64 + k];
            #pragma unroll
            for (int kk = 0; kk < 4; ++kk)
                *(float4*)b[kk] = *(const float4*)&skt[(k + kk) * 64 + ((tx ^ ((k + kk) & 7)) << 2)];
            #pragma unroll
            for (int kk = 0; kk < 4; ++kk)
                #pragma unroll
                for (int i = 0; i < 4; ++i)
                    #pragma unroll
                    for (int c = 0; c < 4; ++c)
                        s[i][c] = fmaf(a[i][kk], b[kk][c], s[i][c]);
        }

        // ---- bias (L1-resident packed LUT) + mask ----
        #pragma unroll
        for (int i = 0; i < 4; ++i) {
            size_t rowoff = ((size_t)head * SS + (size_t)(i0 + r0 + i)) * SS + (size_t)(j0 + c0);
            float4 d4 = *(const float4*)(dist + rowoff);
            float4 e4 = *(const float4*)(ener + rowoff);
            int4  mk4 = *(const int4*)(mask + rowoff);
            float dx[4] = {d4.x, d4.y, d4.z, d4.w};
            float ex[4] = {e4.x, e4.y, e4.z, e4.w};
            int   mm[4] = {mk4.x, mk4.y, mk4.z, mk4.w};
            #pragma unroll
            for (int c = 0; c < 4; ++c) {
                float v = s[i][c];
                float u = (dx[c] - loD) * ihD;
                u = fminf(fmaxf(u, 0.f), (float)(LUTN - 1));
                int ii = min((int)u, LUTN - 2);
                float fr = u - (float)ii;
                float2 pd = __ldg(&g_lut2D[ii]);
                v += fmaf(pd.y - pd.x, fr, pd.x);

                u = (ex[c] - loE) * ihE;
                u = fminf(fmaxf(u, 0.f), (float)(LUTN - 1));
                ii = min((int)u, LUTN - 2);
                fr = u - (float)ii;
                float2 pe = __ldg(&g_lut2E[ii]);
                v += fmaf(pe.y - pe.x, fr, pe.x);

                s[i][c] = (mm[c] == 0) ? -1e9f : v;
            }
        }

        // ---- online softmax (row stats reduced across the 16 tx lanes) ----
        #pragma unroll
        for (int i = 0; i < 4; ++i) {
            float rmax = fmaxf(fmaxf(s[i][0], s[i][1]), fmaxf(s[i][2], s[i][3]));
            #pragma unroll
            for (int ofs = 8; ofs >= 1; ofs >>= 1)
                rmax = fmaxf(rmax, __shfl_xor_sync(0xffffffffu, rmax, ofs));
            float mnew = fmaxf(mrow[i], rmax);
            float corr = __expf(mrow[i] - mnew);
            mrow[i] = mnew;
            float p0 = __expf(s[i][0] - mnew);
            float p1 = __expf(s[i][1] - mnew);
            float p2 = __expf(s[i][2] - mnew);
            float p3 = __expf(s[i][3] - mnew);
            float rs = (p0 + p1) + (p2 + p3);
            #pragma unroll
            for (int ofs = 8; ofs >= 1; ofs >>= 1)
                rs += __shfl_xor_sync(0xffffffffu, rs, ofs);
            lrow[i] = lrow[i] * corr + rs;
            #pragma unroll
            for (int d = 0; d < 4; ++d) acc[i][d] *= corr;
            int r = r0 + i;
            ((float4*)sp)[r * 16 + (tx ^ (r & 7))] = make_float4(p0, p1, p2, p3);
        }
        __syncthreads();

        // ---- acc += P @ V ----
        #pragma unroll 4
        for (int j = 0; j < BN; j += 4) {
            float p[4][4], vv[4][4];
            #pragma unroll
            for (int i = 0; i < 4; ++i) {
                int r = r0 + i;
                *(float4*)p[i] = ((const float4*)sp)[r * 16 + ((j >> 2) ^ (r & 7))];
            }
            #pragma unroll
            for (int jj = 0; jj < 4; ++jj) {
                int vr = j + jj;
                *(float4*)vv[jj] = ((const float4*)sv)[vr * 16 + (tx ^ (vr & 7))];
            }
            #pragma unroll
            for (int jj = 0; jj < 4; ++jj)
                #pragma unroll
                for (int i = 0; i < 4; ++i)
                    #pragma unroll
                    for (int d = 0; d < 4; ++d)
                        acc[i][d] = fmaf(p[i][jj], vv[jj][d], acc[i][d]);
        }
    }

    // ---- store unnormalized partial + row stats ----
    #pragma unroll
    for (int i = 0; i < 4; ++i) {
        int row = i0 + r0 + i;
        *(float4*)&g_pacc[z][head][row][c0] =
            make_float4(acc[i][0], acc[i][1], acc[i][2], acc[i][3]);
        if (tx == 0) {
            g_pm[z][head][row] = mrow[i];
            g_pl[z][head][row] = lrow[i];
        }
    }
}

// ---------------------------------------------------------------------------
// Kernel 3: merge the SPLIT partials.
// out = sum_z acc_z * e^{m_z - m*} / sum_z l_z * e^{m_z - m*}
// ---------------------------------------------------------------------------
__global__ void merge_kernel(float* __restrict__ out)
{
    int idx = blockIdx.x * blockDim.x + threadIdx.x;   // over NH*SS*(DH/4)
    int d4  = idx & (DH / 4 - 1);
    int rh  = idx >> 4;
    int row = rh & (SS - 1);
    int h   = rh >> 10;

    float m0 = g_pm[0][h][row], m1 = g_pm[1][h][row];
    float l0 = g_pl[0][h][row], l1 = g_pl[1][h][row];
    float mx = fmaxf(m0, m1);
    float a0 = __expf(m0 - mx), a1 = __expf(m1 - mx);
    float inv = 1.0f / (l0 * a0 + l1 * a1);
    float s0 = a0 * inv, s1 = a1 * inv;

    float4 x0 = *(const float4*)&g_pacc[0][h][row][d4 << 2];
    float4 x1 = *(const float4*)&g_pacc[1][h][row][d4 << 2];
    float4 o = make_float4(x0.x * s0 + x1.x * s1,
                           x0.y * s0 + x1.y * s1,
                           x0.z * s0 + x1.z * s1,
                           x0.w * s0 + x1.w * s1);
    *(float4*)(out + ((size_t)(h * SS + row) * DH) + (d4 << 2)) = o;
}

// ---------------------------------------------------------------------------
// Launch
// ---------------------------------------------------------------------------
extern "C" void kernel_launch(void* const* d_in, const int* in_sizes, int n_in,
                              void* d_out, int out_size) {
    const float* Q    = (const float*)d_in[0];
    const float* K    = (const float*)d_in[1];
    const float* V    = (const float*)d_in[2];
    const float* dist = (const float*)d_in[3];
    const float* ener = (const float*)d_in[4];
    const int*   mask = (const int*)d_in[5];
    const float* muD  = (const float*)d_in[6];
    const float* sgD  = (const float*)d_in[7];
    const float* bD   = (const float*)d_in[8];
    const float* muE  = (const float*)d_in[9];
    const float* sgE  = (const float*)d_in[10];
    const float* bE   = (const float*)d_in[11];
    const float* W1   = (const float*)d_in[12];
    const float* b1   = (const float*)d_in[13];
    const float* W2   = (const float*)d_in[14];
    const float* b2   = (const float*)d_in[15];
    float* out = (float*)d_out;

    build_lut_kernel<<<2, 256>>>(muD, sgD, bD, muE, sgE, bE, W1, b1, W2, b2);

    const int smem_bytes = 16384 * sizeof(float);   // 64 KB
    cudaFuncSetAttribute(attn_kernel, cudaFuncAttributeMaxDynamicSharedMemorySize, smem_bytes);
    dim3 grid(SS / BM, NH, SPLIT);
    attn_kernel<<<grid, 256, smem_bytes>>>(Q, K, V, dist, ener, mask);

    merge_kernel<<<NH * SS * (DH / 4) / 256, 256>>>(out);
}